// round 2
// baseline (speedup 1.0000x reference)
#include <cuda_runtime.h>

#define S_LEN 2048
#define D_DIM 2048
#define NH 32
#define NB 8
#define HB 256   // NH*NB

// -------- scratch (no allocations allowed) --------
__device__ float g_pq[NH * S_LEN * NB];   // [h][s][bit], pre-scaled by 2
__device__ float g_pk[NH * S_LEN * NB];   // [h][s][bit]
__device__ float g_pv[NH * S_LEN * NB];   // [h][s][bit]
__device__ float g_sumk[NH * S_LEN];      // sum over bits of pk
__device__ float g_op[S_LEN * HB];        // (e1-e0) * attn_out, [s][h*8+d]
__device__ float g_bias[D_DIM];           // e0 @ Wo

__device__ __forceinline__ float fsigmoid(float x) {
    return 1.0f / (1.0f + __expf(-x));
}

// ---------------------------------------------------------------
// 128x64 fp32 GEMM tile core: computes C tile (brow..+128, bcol..+64)
// of A(MxK,row-major) @ B(KxN,row-major). 256 threads, acc[8][4]/thread.
// ---------------------------------------------------------------
__device__ __forceinline__ void gemm_tile_128x64(
    const float* __restrict__ A, const float* __restrict__ B,
    int K, int N, int brow, int bcol, float (&acc)[8][4])
{
    __shared__ __align__(16) float As[16][132];  // [k][m], padded
    __shared__ __align__(16) float Bs[16][64];   // [k][n]
    const int tid = threadIdx.x;
    const int tx = tid & 15;     // col group (x4)
    const int ty = tid >> 4;     // row group (x8)

    const int ar = tid >> 2;            // 0..63
    const int ac = (tid & 3) * 4;       // 0,4,8,12
    const int br = tid >> 4;            // 0..15
    const int bc = (tid & 15) * 4;      // 0..60

#pragma unroll
    for (int i = 0; i < 8; ++i)
#pragma unroll
        for (int j = 0; j < 4; ++j) acc[i][j] = 0.0f;

    for (int k0 = 0; k0 < K; k0 += 16) {
        float4 a0 = *(const float4*)&A[(size_t)(brow + ar) * K + k0 + ac];
        float4 a1 = *(const float4*)&A[(size_t)(brow + ar + 64) * K + k0 + ac];
        float4 bv = *(const float4*)&B[(size_t)(k0 + br) * N + bcol + bc];
        As[ac + 0][ar] = a0.x; As[ac + 1][ar] = a0.y;
        As[ac + 2][ar] = a0.z; As[ac + 3][ar] = a0.w;
        As[ac + 0][ar + 64] = a1.x; As[ac + 1][ar + 64] = a1.y;
        As[ac + 2][ar + 64] = a1.z; As[ac + 3][ar + 64] = a1.w;
        *(float4*)&Bs[br][bc] = bv;
        __syncthreads();
#pragma unroll
        for (int k = 0; k < 16; ++k) {
            float4 x0 = *(const float4*)&As[k][ty * 8];
            float4 x1 = *(const float4*)&As[k][ty * 8 + 4];
            float4 y0 = *(const float4*)&Bs[k][tx * 4];
            float a[8] = {x0.x, x0.y, x0.z, x0.w, x1.x, x1.y, x1.z, x1.w};
            float b[4] = {y0.x, y0.y, y0.z, y0.w};
#pragma unroll
            for (int i = 0; i < 8; ++i)
#pragma unroll
                for (int j = 0; j < 4; ++j)
                    acc[i][j] = fmaf(a[i], b[j], acc[i][j]);
        }
        __syncthreads();
    }
}

// ---------------------------------------------------------------
// K1: QKV projections + sigmoid, scatter to [h][s][bit] layout.
// grid (HB/64, S/128, 3)
// ---------------------------------------------------------------
__global__ void __launch_bounds__(256) qkv_kernel(
    const float* __restrict__ hs, const float* __restrict__ Wq,
    const float* __restrict__ Wk, const float* __restrict__ Wv)
{
    const float* B = (blockIdx.z == 0) ? Wq : (blockIdx.z == 1) ? Wk : Wv;
    float* O       = (blockIdx.z == 0) ? g_pq : (blockIdx.z == 1) ? g_pk : g_pv;
    const float scale = (blockIdx.z == 0) ? 2.0f : 1.0f;  // pq pre-scaled by 2
    int brow = blockIdx.y * 128, bcol = blockIdx.x * 64;
    float acc[8][4];
    gemm_tile_128x64(hs, B, D_DIM, HB, brow, bcol, acc);
    int tx = threadIdx.x & 15, ty = threadIdx.x >> 4;
#pragma unroll
    for (int i = 0; i < 8; ++i) {
        int s = brow + ty * 8 + i;
#pragma unroll
        for (int j = 0; j < 4; ++j) {
            int c = bcol + tx * 4 + j;
            int h = c >> 3, d = c & 7;
            O[((size_t)h * S_LEN + s) * NB + d] = scale * fsigmoid(acc[i][j]);
        }
    }
}

// K2: per-(h,s) sum of pk bits
__global__ void sumk_kernel() {
    int idx = blockIdx.x * blockDim.x + threadIdx.x;
    if (idx < NH * S_LEN) {
        const float* p = &g_pk[(size_t)idx * NB];
        float s = 0.f;
#pragma unroll
        for (int d = 0; d < NB; ++d) s += p[d];
        g_sumk[idx] = s;
    }
}

// K3: bias[n] = sum_j e0[j] * Wo[j][n]
__global__ void bias_kernel(const float* __restrict__ e0, const float* __restrict__ Wo) {
    int n = blockIdx.x * blockDim.x + threadIdx.x;
    if (n < D_DIM) {
        float s = 0.f;
        for (int j = 0; j < HB; ++j) s = fmaf(e0[j], Wo[(size_t)j * D_DIM + n], s);
        g_bias[n] = s;
    }
}

// ---------------------------------------------------------------
// K4: causal attention per head. grid (S/128, NH), 128 threads,
// one q-row per thread. Scores bounded (-8,16) -> no online max.
// ---------------------------------------------------------------
__global__ void __launch_bounds__(128) attn_kernel(
    const float* __restrict__ e0, const float* __restrict__ e1)
{
    const int h = blockIdx.y;
    const int qt = blockIdx.x;
    const int tid = threadIdx.x;
    const int q = qt * 128 + tid;

    __shared__ __align__(16) float sk[128 * 8];
    __shared__ __align__(16) float sv[128 * 8];
    __shared__ float ssum[128];

    float pq[8];
    {
        const float4* p = (const float4*)&g_pq[((size_t)h * S_LEN + q) * NB];
        float4 p0 = p[0], p1 = p[1];
        pq[0] = p0.x; pq[1] = p0.y; pq[2] = p0.z; pq[3] = p0.w;
        pq[4] = p1.x; pq[5] = p1.y; pq[6] = p1.z; pq[7] = p1.w;
    }
    float acc[8] = {0, 0, 0, 0, 0, 0, 0, 0};
    float l = 0.f;

    const float* kbase = &g_pk[(size_t)h * S_LEN * NB];
    const float* vbase = &g_pv[(size_t)h * S_LEN * NB];

    for (int kt = 0; kt <= qt; ++kt) {
        const float4* kp = (const float4*)(kbase + (size_t)kt * 128 * NB);
        const float4* vp = (const float4*)(vbase + (size_t)kt * 128 * NB);
        ((float4*)sk)[tid]       = kp[tid];
        ((float4*)sk)[tid + 128] = kp[tid + 128];
        ((float4*)sv)[tid]       = vp[tid];
        ((float4*)sv)[tid + 128] = vp[tid + 128];
        ssum[tid] = g_sumk[h * S_LEN + kt * 128 + tid];
        __syncthreads();

        const int kmax = (kt == qt) ? (tid + 1) : 128;
        const float4* sk4 = (const float4*)sk;
        const float4* sv4 = (const float4*)sv;
        for (int kk = 0; kk < kmax; ++kk) {
            float4 k0 = sk4[kk * 2];
            float4 k1 = sk4[kk * 2 + 1];
            float dot = -ssum[kk];
            dot = fmaf(pq[0], k0.x, dot); dot = fmaf(pq[1], k0.y, dot);
            dot = fmaf(pq[2], k0.z, dot); dot = fmaf(pq[3], k0.w, dot);
            dot = fmaf(pq[4], k1.x, dot); dot = fmaf(pq[5], k1.y, dot);
            dot = fmaf(pq[6], k1.z, dot); dot = fmaf(pq[7], k1.w, dot);
            float e = __expf(dot);  // pq pre-scaled by 2 -> dot = 2<pq,pk> - sumk
            l += e;
            float4 v0 = sv4[kk * 2];
            float4 v1 = sv4[kk * 2 + 1];
            acc[0] = fmaf(e, v0.x, acc[0]); acc[1] = fmaf(e, v0.y, acc[1]);
            acc[2] = fmaf(e, v0.z, acc[2]); acc[3] = fmaf(e, v0.w, acc[3]);
            acc[4] = fmaf(e, v1.x, acc[4]); acc[5] = fmaf(e, v1.y, acc[5]);
            acc[6] = fmaf(e, v1.z, acc[6]); acc[7] = fmaf(e, v1.w, acc[7]);
        }
        __syncthreads();
    }

    float inv = 1.0f / l;
    float o[8];
#pragma unroll
    for (int d = 0; d < 8; ++d) {
        int j = h * 8 + d;
        o[d] = acc[d] * inv * (e1[j] - e0[j]);
    }
    float4* outp = (float4*)&g_op[(size_t)q * HB + h * 8];
    outp[0] = make_float4(o[0], o[1], o[2], o[3]);
    outp[1] = make_float4(o[4], o[5], o[6], o[7]);
}

// K5: gate pre-activation hs @ Wg -> d_out (raw)
__global__ void __launch_bounds__(256) gate_kernel(
    const float* __restrict__ hs, const float* __restrict__ Wg,
    float* __restrict__ out)
{
    int brow = blockIdx.y * 128, bcol = blockIdx.x * 64;
    float acc[8][4];
    gemm_tile_128x64(hs, Wg, D_DIM, D_DIM, brow, bcol, acc);
    int tx = threadIdx.x & 15, ty = threadIdx.x >> 4;
#pragma unroll
    for (int i = 0; i < 8; ++i) {
        int r = brow + ty * 8 + i;
        *(float4*)&out[(size_t)r * D_DIM + bcol + tx * 4] =
            make_float4(acc[i][0], acc[i][1], acc[i][2], acc[i][3]);
    }
}

// K6: out = (g_op @ Wo + bias) * sigmoid(gate_pre)
__global__ void __launch_bounds__(256) final_kernel(
    const float* __restrict__ Wo, float* __restrict__ out)
{
    int brow = blockIdx.y * 128, bcol = blockIdx.x * 64;
    float acc[8][4];
    gemm_tile_128x64(g_op, Wo, HB, D_DIM, brow, bcol, acc);
    int tx = threadIdx.x & 15, ty = threadIdx.x >> 4;
    int c0 = bcol + tx * 4;
    float b0 = g_bias[c0], b1 = g_bias[c0 + 1], b2 = g_bias[c0 + 2], b3 = g_bias[c0 + 3];
#pragma unroll
    for (int i = 0; i < 8; ++i) {
        int r = brow + ty * 8 + i;
        size_t base = (size_t)r * D_DIM + c0;
        float4 g = *(float4*)&out[base];
        float4 v;
        v.x = (acc[i][0] + b0) * fsigmoid(g.x);
        v.y = (acc[i][1] + b1) * fsigmoid(g.y);
        v.z = (acc[i][2] + b2) * fsigmoid(g.z);
        v.w = (acc[i][3] + b3) * fsigmoid(g.w);
        *(float4*)&out[base] = v;
    }
}

extern "C" void kernel_launch(void* const* d_in, const int* in_sizes, int n_in,
                              void* d_out, int out_size)
{
    (void)in_sizes; (void)n_in; (void)out_size;
    const float* hs = (const float*)d_in[0];
    const float* Wq = (const float*)d_in[1];
    const float* Wk = (const float*)d_in[2];
    const float* Wv = (const float*)d_in[3];
    const float* Wo = (const float*)d_in[4];
    const float* Wg = (const float*)d_in[5];
    const float* e0 = (const float*)d_in[6];
    const float* e1 = (const float*)d_in[7];
    float* out = (float*)d_out;

    dim3 gq(HB / 64, S_LEN / 128, 3);
    qkv_kernel<<<gq, 256>>>(hs, Wq, Wk, Wv);
    sumk_kernel<<<(NH * S_LEN + 255) / 256, 256>>>();
    bias_kernel<<<(D_DIM + 255) / 256, 256>>>(e0, Wo);
    dim3 gg(D_DIM / 64, S_LEN / 128);
    gate_kernel<<<gg, 256>>>(hs, Wg, out);
    dim3 ga(S_LEN / 128, NH);
    attn_kernel<<<ga, 128>>>(e0, e1);
    final_kernel<<<gg, 256>>>(Wo, out);
}

// round 3
// speedup vs baseline: 1.0005x; 1.0005x over previous
#include <cuda_runtime.h>

#define S_LEN 2048
#define D_DIM 2048
#define NH 32
#define NB 8
#define HB 256   // NH*NB

// -------- scratch (no allocations allowed) --------
__device__ float g_pq[NH * S_LEN * NB];   // [h][s][bit], pre-scaled by 2
__device__ float g_pk[NH * S_LEN * NB];   // [h][s][bit]
__device__ float g_pv[NH * S_LEN * NB];   // [h][s][bit]
__device__ float g_sumk[NH * S_LEN];      // sum over bits of pk
__device__ float g_op[S_LEN * HB];        // (e1-e0) * attn_out, [s][h*8+d]
__device__ float g_bias[D_DIM];           // e0 @ Wo

__device__ __forceinline__ float fsigmoid(float x) {
    return 1.0f / (1.0f + __expf(-x));
}

// ---------------------------------------------------------------
// 128x64 fp32 GEMM tile core: computes C tile (brow..+128, bcol..+64)
// of A(MxK,row-major) @ B(KxN,row-major). 256 threads, acc[8][4]/thread.
// ---------------------------------------------------------------
__device__ __forceinline__ void gemm_tile_128x64(
    const float* __restrict__ A, const float* __restrict__ B,
    int K, int N, int brow, int bcol, float (&acc)[8][4])
{
    __shared__ __align__(16) float As[16][132];  // [k][m], padded
    __shared__ __align__(16) float Bs[16][64];   // [k][n]
    const int tid = threadIdx.x;
    const int tx = tid & 15;     // col group (x4)
    const int ty = tid >> 4;     // row group (x8)

    const int ar = tid >> 2;            // 0..63
    const int ac = (tid & 3) * 4;       // 0,4,8,12
    const int br = tid >> 4;            // 0..15
    const int bc = (tid & 15) * 4;      // 0..60

#pragma unroll
    for (int i = 0; i < 8; ++i)
#pragma unroll
        for (int j = 0; j < 4; ++j) acc[i][j] = 0.0f;

    for (int k0 = 0; k0 < K; k0 += 16) {
        float4 a0 = *(const float4*)&A[(size_t)(brow + ar) * K + k0 + ac];
        float4 a1 = *(const float4*)&A[(size_t)(brow + ar + 64) * K + k0 + ac];
        float4 bv = *(const float4*)&B[(size_t)(k0 + br) * N + bcol + bc];
        As[ac + 0][ar] = a0.x; As[ac + 1][ar] = a0.y;
        As[ac + 2][ar] = a0.z; As[ac + 3][ar] = a0.w;
        As[ac + 0][ar + 64] = a1.x; As[ac + 1][ar + 64] = a1.y;
        As[ac + 2][ar + 64] = a1.z; As[ac + 3][ar + 64] = a1.w;
        *(float4*)&Bs[br][bc] = bv;
        __syncthreads();
#pragma unroll
        for (int k = 0; k < 16; ++k) {
            float4 x0 = *(const float4*)&As[k][ty * 8];
            float4 x1 = *(const float4*)&As[k][ty * 8 + 4];
            float4 y0 = *(const float4*)&Bs[k][tx * 4];
            float a[8] = {x0.x, x0.y, x0.z, x0.w, x1.x, x1.y, x1.z, x1.w};
            float b[4] = {y0.x, y0.y, y0.z, y0.w};
#pragma unroll
            for (int i = 0; i < 8; ++i)
#pragma unroll
                for (int j = 0; j < 4; ++j)
                    acc[i][j] = fmaf(a[i], b[j], acc[i][j]);
        }
        __syncthreads();
    }
}

// ---------------------------------------------------------------
// K1: QKV projections + sigmoid, scatter to [h][s][bit] layout.
// grid (HB/64, S/128, 3)
// ---------------------------------------------------------------
__global__ void __launch_bounds__(256) qkv_kernel(
    const float* __restrict__ hs, const float* __restrict__ Wq,
    const float* __restrict__ Wk, const float* __restrict__ Wv)
{
    const float* B = (blockIdx.z == 0) ? Wq : (blockIdx.z == 1) ? Wk : Wv;
    float* O       = (blockIdx.z == 0) ? g_pq : (blockIdx.z == 1) ? g_pk : g_pv;
    const float scale = (blockIdx.z == 0) ? 2.0f : 1.0f;  // pq pre-scaled by 2
    int brow = blockIdx.y * 128, bcol = blockIdx.x * 64;
    float acc[8][4];
    gemm_tile_128x64(hs, B, D_DIM, HB, brow, bcol, acc);
    int tx = threadIdx.x & 15, ty = threadIdx.x >> 4;
#pragma unroll
    for (int i = 0; i < 8; ++i) {
        int s = brow + ty * 8 + i;
#pragma unroll
        for (int j = 0; j < 4; ++j) {
            int c = bcol + tx * 4 + j;
            int h = c >> 3, d = c & 7;
            O[((size_t)h * S_LEN + s) * NB + d] = scale * fsigmoid(acc[i][j]);
        }
    }
}

// K2: per-(h,s) sum of pk bits
__global__ void sumk_kernel() {
    int idx = blockIdx.x * blockDim.x + threadIdx.x;
    if (idx < NH * S_LEN) {
        const float* p = &g_pk[(size_t)idx * NB];
        float s = 0.f;
#pragma unroll
        for (int d = 0; d < NB; ++d) s += p[d];
        g_sumk[idx] = s;
    }
}

// K3: bias[n] = sum_j e0[j] * Wo[j][n]
__global__ void bias_kernel(const float* __restrict__ e0, const float* __restrict__ Wo) {
    int n = blockIdx.x * blockDim.x + threadIdx.x;
    if (n < D_DIM) {
        float s = 0.f;
        for (int j = 0; j < HB; ++j) s = fmaf(e0[j], Wo[(size_t)j * D_DIM + n], s);
        g_bias[n] = s;
    }
}

// ---------------------------------------------------------------
// K4: causal attention per head. grid (S/128, NH), 128 threads,
// one q-row per thread. Scores bounded (-8,16) -> no online max.
// ---------------------------------------------------------------
__global__ void __launch_bounds__(128) attn_kernel(
    const float* __restrict__ e0, const float* __restrict__ e1)
{
    const int h = blockIdx.y;
    const int qt = blockIdx.x;
    const int tid = threadIdx.x;
    const int q = qt * 128 + tid;

    __shared__ __align__(16) float sk[128 * 8];
    __shared__ __align__(16) float sv[128 * 8];
    __shared__ float ssum[128];

    float pq[8];
    {
        const float4* p = (const float4*)&g_pq[((size_t)h * S_LEN + q) * NB];
        float4 p0 = p[0], p1 = p[1];
        pq[0] = p0.x; pq[1] = p0.y; pq[2] = p0.z; pq[3] = p0.w;
        pq[4] = p1.x; pq[5] = p1.y; pq[6] = p1.z; pq[7] = p1.w;
    }
    float acc[8] = {0, 0, 0, 0, 0, 0, 0, 0};
    float l = 0.f;

    const float* kbase = &g_pk[(size_t)h * S_LEN * NB];
    const float* vbase = &g_pv[(size_t)h * S_LEN * NB];

    for (int kt = 0; kt <= qt; ++kt) {
        const float4* kp = (const float4*)(kbase + (size_t)kt * 128 * NB);
        const float4* vp = (const float4*)(vbase + (size_t)kt * 128 * NB);
        ((float4*)sk)[tid]       = kp[tid];
        ((float4*)sk)[tid + 128] = kp[tid + 128];
        ((float4*)sv)[tid]       = vp[tid];
        ((float4*)sv)[tid + 128] = vp[tid + 128];
        ssum[tid] = g_sumk[h * S_LEN + kt * 128 + tid];
        __syncthreads();

        const int kmax = (kt == qt) ? (tid + 1) : 128;
        const float4* sk4 = (const float4*)sk;
        const float4* sv4 = (const float4*)sv;
        for (int kk = 0; kk < kmax; ++kk) {
            float4 k0 = sk4[kk * 2];
            float4 k1 = sk4[kk * 2 + 1];
            float dot = -ssum[kk];
            dot = fmaf(pq[0], k0.x, dot); dot = fmaf(pq[1], k0.y, dot);
            dot = fmaf(pq[2], k0.z, dot); dot = fmaf(pq[3], k0.w, dot);
            dot = fmaf(pq[4], k1.x, dot); dot = fmaf(pq[5], k1.y, dot);
            dot = fmaf(pq[6], k1.z, dot); dot = fmaf(pq[7], k1.w, dot);
            float e = __expf(dot);  // pq pre-scaled by 2 -> dot = 2<pq,pk> - sumk
            l += e;
            float4 v0 = sv4[kk * 2];
            float4 v1 = sv4[kk * 2 + 1];
            acc[0] = fmaf(e, v0.x, acc[0]); acc[1] = fmaf(e, v0.y, acc[1]);
            acc[2] = fmaf(e, v0.z, acc[2]); acc[3] = fmaf(e, v0.w, acc[3]);
            acc[4] = fmaf(e, v1.x, acc[4]); acc[5] = fmaf(e, v1.y, acc[5]);
            acc[6] = fmaf(e, v1.z, acc[6]); acc[7] = fmaf(e, v1.w, acc[7]);
        }
        __syncthreads();
    }

    float inv = 1.0f / l;
    float o[8];
#pragma unroll
    for (int d = 0; d < 8; ++d) {
        int j = h * 8 + d;
        o[d] = acc[d] * inv * (e1[j] - e0[j]);
    }
    float4* outp = (float4*)&g_op[(size_t)q * HB + h * 8];
    outp[0] = make_float4(o[0], o[1], o[2], o[3]);
    outp[1] = make_float4(o[4], o[5], o[6], o[7]);
}

// K5: gate pre-activation hs @ Wg -> d_out (raw)
__global__ void __launch_bounds__(256) gate_kernel(
    const float* __restrict__ hs, const float* __restrict__ Wg,
    float* __restrict__ out)
{
    int brow = blockIdx.y * 128, bcol = blockIdx.x * 64;
    float acc[8][4];
    gemm_tile_128x64(hs, Wg, D_DIM, D_DIM, brow, bcol, acc);
    int tx = threadIdx.x & 15, ty = threadIdx.x >> 4;
#pragma unroll
    for (int i = 0; i < 8; ++i) {
        int r = brow + ty * 8 + i;
        *(float4*)&out[(size_t)r * D_DIM + bcol + tx * 4] =
            make_float4(acc[i][0], acc[i][1], acc[i][2], acc[i][3]);
    }
}

// K6: out = (g_op @ Wo + bias) * sigmoid(gate_pre)
__global__ void __launch_bounds__(256) final_kernel(
    const float* __restrict__ Wo, float* __restrict__ out)
{
    int brow = blockIdx.y * 128, bcol = blockIdx.x * 64;
    float acc[8][4];
    gemm_tile_128x64(g_op, Wo, HB, D_DIM, brow, bcol, acc);
    int tx = threadIdx.x & 15, ty = threadIdx.x >> 4;
    int c0 = bcol + tx * 4;
    float b0 = g_bias[c0], b1 = g_bias[c0 + 1], b2 = g_bias[c0 + 2], b3 = g_bias[c0 + 3];
#pragma unroll
    for (int i = 0; i < 8; ++i) {
        int r = brow + ty * 8 + i;
        size_t base = (size_t)r * D_DIM + c0;
        float4 g = *(float4*)&out[base];
        float4 v;
        v.x = (acc[i][0] + b0) * fsigmoid(g.x);
        v.y = (acc[i][1] + b1) * fsigmoid(g.y);
        v.z = (acc[i][2] + b2) * fsigmoid(g.z);
        v.w = (acc[i][3] + b3) * fsigmoid(g.w);
        *(float4*)&out[base] = v;
    }
}

extern "C" void kernel_launch(void* const* d_in, const int* in_sizes, int n_in,
                              void* d_out, int out_size)
{
    (void)in_sizes; (void)n_in; (void)out_size;
    const float* hs = (const float*)d_in[0];
    const float* Wq = (const float*)d_in[1];
    const float* Wk = (const float*)d_in[2];
    const float* Wv = (const float*)d_in[3];
    const float* Wo = (const float*)d_in[4];
    const float* Wg = (const float*)d_in[5];
    const float* e0 = (const float*)d_in[6];
    const float* e1 = (const float*)d_in[7];
    float* out = (float*)d_out;

    dim3 gq(HB / 64, S_LEN / 128, 3);
    qkv_kernel<<<gq, 256>>>(hs, Wq, Wk, Wv);
    sumk_kernel<<<(NH * S_LEN + 255) / 256, 256>>>();
    bias_kernel<<<(D_DIM + 255) / 256, 256>>>(e0, Wo);
    dim3 gg(D_DIM / 64, S_LEN / 128);
    gate_kernel<<<gg, 256>>>(hs, Wg, out);
    dim3 ga(S_LEN / 128, NH);
    attn_kernel<<<ga, 128>>>(e0, e1);
    final_kernel<<<gg, 256>>>(Wo, out);
}